// round 1
// baseline (speedup 1.0000x reference)
#include <cuda_runtime.h>
#include <cuda_bf16.h>
#include <math.h>

// Problem constants
#define Bc 32
#define Sc 512
#define Hc 768
#define Lc 6
#define NHc 12
#define FFc 3072
#define Tc 7
#define DHc 64
#define BSc (Bc*Sc)          // 16384

// ---------------- scratch buffers (device globals; no allocation allowed) ----
__device__ float g_x  [(size_t)BSc*Hc];
__device__ float g_y  [(size_t)BSc*Hc];
__device__ float g_q  [(size_t)BSc*Hc];
__device__ float g_k  [(size_t)BSc*Hc];
__device__ float g_v  [(size_t)BSc*Hc];
__device__ float g_ctx[(size_t)BSc*Hc];
__device__ float g_sc [(size_t)Bc*NHc*Sc*Sc];   // 402 MB
__device__ float g_h  [(size_t)BSc*FFc];        // 201 MB
__device__ float g_em [(size_t)BSc*Tc];
__device__ float g_num[Bc];
__device__ float g_den[Bc];

// ---------------- helpers ----------------------------------------------------
__device__ __forceinline__ float block_reduce_sum(float v, float* sbuf) {
    int tid = threadIdx.x;
    int lane = tid & 31, warp = tid >> 5;
    int nw = (blockDim.x + 31) >> 5;
    #pragma unroll
    for (int o = 16; o > 0; o >>= 1) v += __shfl_xor_sync(0xffffffffu, v, o);
    __syncthreads();
    if (lane == 0) sbuf[warp] = v;
    __syncthreads();
    if (warp == 0) {
        float w = (lane < nw) ? sbuf[lane] : 0.f;
        #pragma unroll
        for (int o = 16; o > 0; o >>= 1) w += __shfl_xor_sync(0xffffffffu, w, o);
        if (lane == 0) sbuf[0] = w;
    }
    __syncthreads();
    return sbuf[0];
}

__device__ __forceinline__ float gelu_exact(float x) {
    return 0.5f * x * (1.0f + erff(x * 0.70710678118654752f));
}

// ---------------- embedding + layernorm --------------------------------------
__global__ void embed_ln_kernel(const float* __restrict__ wemb,
                                const float* __restrict__ pemb,
                                const float* __restrict__ g,
                                const float* __restrict__ bt,
                                const int*   __restrict__ ids,
                                float* __restrict__ x)
{
    int token = blockIdx.x;
    int s = token % Sc;
    int id = ids[token];
    __shared__ float buf[Hc];
    __shared__ float sbuf[32];
    float lsum = 0.f, lsum2 = 0.f;
    for (int c = threadIdx.x; c < Hc; c += blockDim.x) {
        float vv = wemb[(size_t)id*Hc + c] + pemb[(size_t)s*Hc + c];
        buf[c] = vv; lsum += vv; lsum2 += vv*vv;
    }
    float sum  = block_reduce_sum(lsum,  sbuf);
    float sum2 = block_reduce_sum(lsum2, sbuf);
    float mean = sum * (1.0f/Hc);
    float var  = sum2 * (1.0f/Hc) - mean*mean;
    float inv  = rsqrtf(var + 1e-12f);
    size_t base = (size_t)token*Hc;
    for (int c = threadIdx.x; c < Hc; c += blockDim.x)
        x[base + c] = (buf[c] - mean) * inv * g[c] + bt[c];
}

// ---------------- add-residual + layernorm (x = LN(x + y)) -------------------
__global__ void add_ln_kernel(float* __restrict__ x, const float* __restrict__ y,
                              const float* __restrict__ g, const float* __restrict__ bt)
{
    int token = blockIdx.x;
    __shared__ float buf[Hc];
    __shared__ float sbuf[32];
    size_t base = (size_t)token*Hc;
    float lsum = 0.f, lsum2 = 0.f;
    for (int c = threadIdx.x; c < Hc; c += blockDim.x) {
        float vv = x[base + c] + y[base + c];
        buf[c] = vv; lsum += vv; lsum2 += vv*vv;
    }
    float sum  = block_reduce_sum(lsum,  sbuf);
    float sum2 = block_reduce_sum(lsum2, sbuf);
    float mean = sum * (1.0f/Hc);
    float var  = sum2 * (1.0f/Hc) - mean*mean;
    float inv  = rsqrtf(var + 1e-12f);
    for (int c = threadIdx.x; c < Hc; c += blockDim.x)
        x[base + c] = (buf[c] - mean) * inv * g[c] + bt[c];
}

// ---------------- SGEMM: C = act(A @ W + bias) --------------------------------
// A: M x K row-major, W: K x N row-major, C: M x N row-major.
// 128x128 tile, BK=8, 256 threads, 8x8 per thread. M%128==0, N%128==0, K%8==0.
__global__ __launch_bounds__(256) void sgemm128(const float* __restrict__ A,
                                                const float* __restrict__ W,
                                                const float* __restrict__ bias,
                                                float* __restrict__ C,
                                                int M, int N, int K, int act)
{
    __shared__ float As[8][128];
    __shared__ float Bs[8][128];
    const int tid = threadIdx.x;
    const int bx = blockIdx.x, by = blockIdx.y;
    const int tx = tid & 15, ty = tid >> 4;
    const int arow = tid >> 1, acol = (tid & 1) * 4;
    const int brow = tid >> 5, bcol = (tid & 31) * 4;

    const float* Aptr = A + (size_t)(by*128 + arow)*K + acol;
    const float* Bptr = W + (size_t)brow*N + bx*128 + bcol;

    float acc[8][8];
    #pragma unroll
    for (int i = 0; i < 8; i++)
        #pragma unroll
        for (int j = 0; j < 8; j++) acc[i][j] = 0.f;

    for (int k0 = 0; k0 < K; k0 += 8) {
        float4 av = *(const float4*)(Aptr + k0);
        As[acol+0][arow] = av.x;
        As[acol+1][arow] = av.y;
        As[acol+2][arow] = av.z;
        As[acol+3][arow] = av.w;
        float4 bv = *(const float4*)(Bptr + (size_t)k0*N);
        *(float4*)&Bs[brow][bcol] = bv;
        __syncthreads();
        #pragma unroll
        for (int kk = 0; kk < 8; kk++) {
            float a[8], b[8];
            #pragma unroll
            for (int i = 0; i < 8; i++) a[i] = As[kk][ty*8 + i];
            #pragma unroll
            for (int j = 0; j < 8; j++) b[j] = Bs[kk][tx*8 + j];
            #pragma unroll
            for (int i = 0; i < 8; i++)
                #pragma unroll
                for (int j = 0; j < 8; j++) acc[i][j] += a[i]*b[j];
        }
        __syncthreads();
    }

    int col0 = bx*128 + tx*8;
    float bb[8];
    #pragma unroll
    for (int j = 0; j < 8; j++) bb[j] = bias[col0 + j];
    #pragma unroll
    for (int i = 0; i < 8; i++) {
        int row = by*128 + ty*8 + i;
        float o[8];
        #pragma unroll
        for (int j = 0; j < 8; j++) {
            float vv = acc[i][j] + bb[j];
            o[j] = (act == 1) ? gelu_exact(vv) : vv;
        }
        float4* cp = (float4*)(C + (size_t)row*N + col0);
        cp[0] = make_float4(o[0], o[1], o[2], o[3]);
        cp[1] = make_float4(o[4], o[5], o[6], o[7]);
    }
}

// ---------------- attention scores: sc[bh,i,j] = (q_i . k_j)/8 ----------------
__global__ __launch_bounds__(256) void attn_scores_kernel(const float* __restrict__ q,
                                                          const float* __restrict__ k,
                                                          float* __restrict__ sc)
{
    int bh = blockIdx.z;
    int b = bh / NHc, h = bh % NHc;
    const float* qb = q + (size_t)b*Sc*Hc + h*DHc;
    const float* kb = k + (size_t)b*Sc*Hc + h*DHc;
    __shared__ float Qs[8][128];
    __shared__ float Ks[8][128];
    const int tid = threadIdx.x;
    const int tx = tid & 15, ty = tid >> 4;
    const int lrow = tid >> 1, lcol = (tid & 1) * 4;
    int i0 = blockIdx.y * 128, j0 = blockIdx.x * 128;

    float acc[8][8];
    #pragma unroll
    for (int i = 0; i < 8; i++)
        #pragma unroll
        for (int j = 0; j < 8; j++) acc[i][j] = 0.f;

    for (int d0 = 0; d0 < DHc; d0 += 8) {
        float4 qv = *(const float4*)(qb + (size_t)(i0+lrow)*Hc + d0 + lcol);
        Qs[lcol+0][lrow] = qv.x; Qs[lcol+1][lrow] = qv.y;
        Qs[lcol+2][lrow] = qv.z; Qs[lcol+3][lrow] = qv.w;
        float4 kv = *(const float4*)(kb + (size_t)(j0+lrow)*Hc + d0 + lcol);
        Ks[lcol+0][lrow] = kv.x; Ks[lcol+1][lrow] = kv.y;
        Ks[lcol+2][lrow] = kv.z; Ks[lcol+3][lrow] = kv.w;
        __syncthreads();
        #pragma unroll
        for (int kk = 0; kk < 8; kk++) {
            float a[8], b2[8];
            #pragma unroll
            for (int i = 0; i < 8; i++) a[i] = Qs[kk][ty*8 + i];
            #pragma unroll
            for (int j = 0; j < 8; j++) b2[j] = Ks[kk][tx*8 + j];
            #pragma unroll
            for (int i = 0; i < 8; i++)
                #pragma unroll
                for (int j = 0; j < 8; j++) acc[i][j] += a[i]*b2[j];
        }
        __syncthreads();
    }

    float* outp = sc + ((size_t)bh*Sc + (i0 + ty*8))*Sc + j0 + tx*8;
    #pragma unroll
    for (int i = 0; i < 8; i++) {
        float4* cp = (float4*)(outp + (size_t)i*Sc);
        cp[0] = make_float4(acc[i][0]*0.125f, acc[i][1]*0.125f, acc[i][2]*0.125f, acc[i][3]*0.125f);
        cp[1] = make_float4(acc[i][4]*0.125f, acc[i][5]*0.125f, acc[i][6]*0.125f, acc[i][7]*0.125f);
    }
}

// ---------------- masked softmax over last dim (row = bh*S + i) ---------------
__global__ __launch_bounds__(128) void softmax_kernel(float* __restrict__ sc,
                                                      const int* __restrict__ amask)
{
    unsigned int row = blockIdx.x;
    int b = (int)(row / Sc) / NHc;
    float* p = sc + (size_t)row * Sc;
    const int* mrow = amask + (size_t)b * Sc;
    int tid = threadIdx.x;

    const float NEG = -3.4028234663852886e+38f;
    float4 vv = ((const float4*)p)[tid];
    int4  mm = ((const int4*)mrow)[tid];
    float v0 = mm.x ? vv.x : NEG;
    float v1 = mm.y ? vv.y : NEG;
    float v2 = mm.z ? vv.z : NEG;
    float v3 = mm.w ? vv.w : NEG;

    __shared__ float sred[32];
    __shared__ float s_stat;
    int lane = tid & 31, warp = tid >> 5;

    float mx = fmaxf(fmaxf(v0, v1), fmaxf(v2, v3));
    #pragma unroll
    for (int o = 16; o > 0; o >>= 1) mx = fmaxf(mx, __shfl_xor_sync(0xffffffffu, mx, o));
    if (lane == 0) sred[warp] = mx;
    __syncthreads();
    if (tid == 0) {
        float m = sred[0];
        for (int w = 1; w < 4; w++) m = fmaxf(m, sred[w]);
        s_stat = m;
    }
    __syncthreads();
    float M = s_stat;

    float e0 = expf(v0 - M), e1 = expf(v1 - M), e2 = expf(v2 - M), e3 = expf(v3 - M);
    float sm = e0 + e1 + e2 + e3;
    #pragma unroll
    for (int o = 16; o > 0; o >>= 1) sm += __shfl_xor_sync(0xffffffffu, sm, o);
    __syncthreads();
    if (lane == 0) sred[warp] = sm;
    __syncthreads();
    if (tid == 0) s_stat = sred[0] + sred[1] + sred[2] + sred[3];
    __syncthreads();
    float inv = 1.0f / s_stat;

    ((float4*)p)[tid] = make_float4(e0*inv, e1*inv, e2*inv, e3*inv);
}

// ---------------- ctx = probs @ v  (per bh, out 128x64 tiles) -----------------
__global__ __launch_bounds__(128) void attn_ctx_kernel(const float* __restrict__ probs,
                                                       const float* __restrict__ v,
                                                       float* __restrict__ ctx)
{
    int bh = blockIdx.y;
    int b = bh / NHc, h = bh % NHc;
    const float* P  = probs + (size_t)bh*Sc*Sc;
    const float* vb = v + (size_t)b*Sc*Hc + h*DHc;
    __shared__ float Ps[8][128];  // [j][i]
    __shared__ float Vs[8][64];   // [j][d]
    const int tid = threadIdx.x;
    const int tx = tid & 7, ty = tid >> 3;
    int i0 = blockIdx.x * 128;

    float acc[8][8];
    #pragma unroll
    for (int i = 0; i < 8; i++)
        #pragma unroll
        for (int j = 0; j < 8; j++) acc[i][j] = 0.f;

    const int vr = tid >> 4, vc = (tid & 15) * 4;

    for (int j0 = 0; j0 < Sc; j0 += 8) {
        const float* prow = P + (size_t)(i0 + tid)*Sc + j0;
        float4 p0 = *(const float4*)(prow);
        float4 p1 = *(const float4*)(prow + 4);
        Ps[0][tid] = p0.x; Ps[1][tid] = p0.y; Ps[2][tid] = p0.z; Ps[3][tid] = p0.w;
        Ps[4][tid] = p1.x; Ps[5][tid] = p1.y; Ps[6][tid] = p1.z; Ps[7][tid] = p1.w;
        float4 vv = *(const float4*)(vb + (size_t)(j0+vr)*Hc + vc);
        *(float4*)&Vs[vr][vc] = vv;
        __syncthreads();
        #pragma unroll
        for (int kk = 0; kk < 8; kk++) {
            float a[8], b2[8];
            #pragma unroll
            for (int i = 0; i < 8; i++) a[i] = Ps[kk][ty*8 + i];
            #pragma unroll
            for (int d = 0; d < 8; d++) b2[d] = Vs[kk][tx*8 + d];
            #pragma unroll
            for (int i = 0; i < 8; i++)
                #pragma unroll
                for (int d = 0; d < 8; d++) acc[i][d] += a[i]*b2[d];
        }
        __syncthreads();
    }

    float* outb = ctx + (size_t)b*Sc*Hc + h*DHc;
    #pragma unroll
    for (int i = 0; i < 8; i++) {
        int row = i0 + ty*8 + i;
        float4* cp = (float4*)(outb + (size_t)row*Hc + tx*8);
        cp[0] = make_float4(acc[i][0], acc[i][1], acc[i][2], acc[i][3]);
        cp[1] = make_float4(acc[i][4], acc[i][5], acc[i][6], acc[i][7]);
    }
}

// ---------------- emissions = x @ cls_w + cls_b (T=7) -------------------------
__global__ void emissions_kernel(const float* __restrict__ x,
                                 const float* __restrict__ cw,
                                 const float* __restrict__ cb,
                                 float* __restrict__ em)
{
    int token = blockIdx.x;
    int w = threadIdx.x >> 5, lane = threadIdx.x & 31;
    const float* xr = x + (size_t)token*Hc;
    float sum = 0.f;
    for (int c = lane; c < Hc; c += 32) sum += xr[c] * cw[(size_t)c*Tc + w];
    #pragma unroll
    for (int o = 16; o > 0; o >>= 1) sum += __shfl_down_sync(0xffffffffu, sum, o);
    if (lane == 0) em[(size_t)token*Tc + w] = sum + cb[w];
}

// ---------------- CRF: numerator (gold path score) + denominator (forward) ----
__global__ void crf_kernel(const float* __restrict__ em,
                           const int*   __restrict__ labels,
                           const float* __restrict__ cstart,
                           const float* __restrict__ cend,
                           const float* __restrict__ ctrans,
                           float* __restrict__ num_out,
                           float* __restrict__ den_out)
{
    __shared__ float tr[Tc*Tc];
    __shared__ float sbuf[32];
    __shared__ int   s_len;
    int b = blockIdx.x, tid = threadIdx.x;
    const int* lab = labels + (size_t)b*Sc;
    const float* e = em + (size_t)b*Sc*Tc;
    if (tid < Tc*Tc) tr[tid] = ctrans[tid];
    __syncthreads();

    float cnt = 0.f, part = 0.f;
    for (int t = tid; t < Sc; t += blockDim.x) {
        bool m = (t == 0) || (lab[t] != -100);
        if (m) cnt += 1.f;
        if (t >= 1 && lab[t] != -100) {
            int cur = lab[t];
            int prv;
            if (t - 1 == 0) { prv = lab[0]; prv = prv < 0 ? 0 : (prv > Tc-1 ? Tc-1 : prv); }
            else            { prv = lab[t-1]; if (prv == -100) prv = 0; }
            part += tr[prv*Tc + cur] + e[(size_t)t*Tc + cur];
        }
    }
    float totc = block_reduce_sum(cnt, sbuf);
    float tot  = block_reduce_sum(part, sbuf);
    if (tid == 0) {
        int len = (int)(totc + 0.5f);
        s_len = len;
        int s0 = lab[0]; s0 = s0 < 0 ? 0 : (s0 > Tc-1 ? Tc-1 : s0);
        float num = cstart[s0] + e[s0] + tot;
        int send = len - 1;
        int sl;
        if (send == 0) sl = s0;
        else { sl = lab[send]; if (sl == -100) sl = 0; }
        num += cend[sl];
        num_out[b] = num;
    }
    __syncthreads();
    int len = s_len;

    if (tid < 32) {
        int j = tid;
        int jj = (j < Tc) ? j : 0;
        float a = cstart[jj] + e[jj];
        for (int t = 1; t < len; t++) {
            float ej = e[(size_t)t*Tc + jj];
            float av[Tc];
            float m = -3.4028235e+38f;
            #pragma unroll
            for (int i = 0; i < Tc; i++) {
                float ai = __shfl_sync(0xffffffffu, a, i);
                float vv = ai + tr[i*Tc + jj];
                av[i] = vv; m = fmaxf(m, vv);
            }
            float ss = 0.f;
            #pragma unroll
            for (int i = 0; i < Tc; i++) ss += expf(av[i] - m);
            float ne = m + logf(ss) + ej;
            a = (j < Tc) ? ne : a;
        }
        float fa = (j < Tc) ? a + cend[jj] : -3.4028235e+38f;
        float mm = fa;
        #pragma unroll
        for (int o = 16; o > 0; o >>= 1) mm = fmaxf(mm, __shfl_xor_sync(0xffffffffu, mm, o));
        float es = (j < Tc) ? expf(fa - mm) : 0.f;
        #pragma unroll
        for (int o = 16; o > 0; o >>= 1) es += __shfl_xor_sync(0xffffffffu, es, o);
        if (tid == 0) den_out[b] = mm + logf(es);
    }
}

// ---------------- final loss ---------------------------------------------------
__global__ void loss_kernel(const float* __restrict__ num,
                            const float* __restrict__ den,
                            float* __restrict__ out)
{
    int tid = threadIdx.x;
    float v = (tid < Bc) ? (num[tid] - den[tid]) : 0.f;
    #pragma unroll
    for (int o = 16; o > 0; o >>= 1) v += __shfl_down_sync(0xffffffffu, v, o);
    if (tid == 0) out[0] = -v / (float)Bc;
}

// ---------------- host launcher ------------------------------------------------
extern "C" void kernel_launch(void* const* d_in, const int* in_sizes, int n_in,
                              void* d_out, int out_size)
{
    const float* word_emb = (const float*)d_in[0];
    const float* pos_emb  = (const float*)d_in[1];
    const float* emb_ln_s = (const float*)d_in[2];
    const float* emb_ln_b = (const float*)d_in[3];
    const float* attn_qw  = (const float*)d_in[4];
    const float* attn_qb  = (const float*)d_in[5];
    const float* attn_kw  = (const float*)d_in[6];
    const float* attn_kb  = (const float*)d_in[7];
    const float* attn_vw  = (const float*)d_in[8];
    const float* attn_vb  = (const float*)d_in[9];
    const float* attn_ow  = (const float*)d_in[10];
    const float* attn_ob  = (const float*)d_in[11];
    const float* ln1_s    = (const float*)d_in[12];
    const float* ln1_b    = (const float*)d_in[13];
    const float* ffn_w1   = (const float*)d_in[14];
    const float* ffn_b1   = (const float*)d_in[15];
    const float* ffn_w2   = (const float*)d_in[16];
    const float* ffn_b2   = (const float*)d_in[17];
    const float* ln2_s    = (const float*)d_in[18];
    const float* ln2_b    = (const float*)d_in[19];
    const float* cls_w    = (const float*)d_in[20];
    const float* cls_b    = (const float*)d_in[21];
    const float* crf_start= (const float*)d_in[22];
    const float* crf_end  = (const float*)d_in[23];
    const float* crf_trans= (const float*)d_in[24];
    const int* input_ids  = (const int*)d_in[25];
    const int* amask      = (const int*)d_in[26];
    const int* labels     = (const int*)d_in[27];

    float *x, *y, *q, *k, *v, *ctx, *sc, *hb, *em, *nb, *db;
    cudaGetSymbolAddress((void**)&x,   g_x);
    cudaGetSymbolAddress((void**)&y,   g_y);
    cudaGetSymbolAddress((void**)&q,   g_q);
    cudaGetSymbolAddress((void**)&k,   g_k);
    cudaGetSymbolAddress((void**)&v,   g_v);
    cudaGetSymbolAddress((void**)&ctx, g_ctx);
    cudaGetSymbolAddress((void**)&sc,  g_sc);
    cudaGetSymbolAddress((void**)&hb,  g_h);
    cudaGetSymbolAddress((void**)&em,  g_em);
    cudaGetSymbolAddress((void**)&nb,  g_num);
    cudaGetSymbolAddress((void**)&db,  g_den);

    embed_ln_kernel<<<BSc, 256>>>(word_emb, pos_emb, emb_ln_s, emb_ln_b, input_ids, x);

    for (int i = 0; i < Lc; i++) {
        size_t wOff = (size_t)i*Hc*Hc, bOff = (size_t)i*Hc;
        dim3 gHH(Hc/128, BSc/128);
        sgemm128<<<gHH, 256>>>(x, attn_qw + wOff, attn_qb + bOff, q, BSc, Hc, Hc, 0);
        sgemm128<<<gHH, 256>>>(x, attn_kw + wOff, attn_kb + bOff, k, BSc, Hc, Hc, 0);
        sgemm128<<<gHH, 256>>>(x, attn_vw + wOff, attn_vb + bOff, v, BSc, Hc, Hc, 0);

        attn_scores_kernel<<<dim3(Sc/128, Sc/128, Bc*NHc), 256>>>(q, k, sc);
        softmax_kernel<<<Bc*NHc*Sc, 128>>>(sc, amask);
        attn_ctx_kernel<<<dim3(Sc/128, Bc*NHc), 128>>>(sc, v, ctx);

        sgemm128<<<gHH, 256>>>(ctx, attn_ow + wOff, attn_ob + bOff, y, BSc, Hc, Hc, 0);
        add_ln_kernel<<<BSc, 256>>>(x, y, ln1_s + bOff, ln1_b + bOff);

        sgemm128<<<dim3(FFc/128, BSc/128), 256>>>(x, ffn_w1 + (size_t)i*Hc*FFc,
                                                  ffn_b1 + (size_t)i*FFc, hb, BSc, FFc, Hc, 1);
        sgemm128<<<gHH, 256>>>(hb, ffn_w2 + (size_t)i*FFc*Hc, ffn_b2 + bOff, y, BSc, Hc, FFc, 0);
        add_ln_kernel<<<BSc, 256>>>(x, y, ln2_s + bOff, ln2_b + bOff);
    }

    emissions_kernel<<<BSc, 224>>>(x, cls_w, cls_b, em);
    crf_kernel<<<Bc, 256>>>(em, labels, crf_start, crf_end, crf_trans, nb, db);
    loss_kernel<<<1, 32>>>(nb, db, (float*)d_out);
}

// round 2
// speedup vs baseline: 5.3970x; 5.3970x over previous
#include <cuda_runtime.h>
#include <cuda_bf16.h>
#include <math.h>

// Problem constants
#define Bc 32
#define Sc 512
#define Hc 768
#define Lc 6
#define NHc 12
#define FFc 3072
#define Tc 7
#define DHc 64
#define BSc (Bc*Sc)          // 16384

// ---------------- scratch buffers (device globals; no allocation allowed) ----
__device__ float          g_x  [(size_t)BSc*Hc];        // fp32 residual stream
__device__ __nv_bfloat16  g_xb [(size_t)BSc*Hc];        // bf16 copy for GEMM input
__device__ float          g_y  [(size_t)BSc*Hc];        // fp32 projection output
__device__ __nv_bfloat16  g_q  [(size_t)BSc*Hc];
__device__ __nv_bfloat16  g_k  [(size_t)BSc*Hc];
__device__ __nv_bfloat16  g_v  [(size_t)BSc*Hc];
__device__ __nv_bfloat16  g_ctx[(size_t)BSc*Hc];
__device__ float          g_sc [(size_t)Bc*NHc*Sc*Sc];  // fp32 scores 402MB
__device__ __nv_bfloat16  g_pb [(size_t)Bc*NHc*Sc*Sc];  // bf16 probs 201MB
__device__ __nv_bfloat16  g_h  [(size_t)BSc*FFc];       // bf16 FFN hidden
__device__ __nv_bfloat16  g_wb [(size_t)(4*Lc*Hc*Hc + 2*Lc*Hc*FFc)]; // bf16 weights
__device__ float          g_em [(size_t)BSc*Tc];
__device__ float          g_num[Bc];
__device__ float          g_den[Bc];

// ---------------- PTX helpers -------------------------------------------------
__device__ __forceinline__ unsigned smem_u32(const void* p) {
    return (unsigned)__cvta_generic_to_shared(p);
}
__device__ __forceinline__ void cp16(unsigned saddr, const void* g) {
    asm volatile("cp.async.cg.shared.global [%0], [%1], 16;\n" :: "r"(saddr), "l"(g));
}
__device__ __forceinline__ void cp_commit() {
    asm volatile("cp.async.commit_group;\n");
}
template<int N>
__device__ __forceinline__ void cp_wait() {
    asm volatile("cp.async.wait_group %0;\n" :: "n"(N));
}
__device__ __forceinline__ void ldsm_x4(unsigned r[4], unsigned addr) {
    asm volatile("ldmatrix.sync.aligned.m8n8.x4.shared.b16 {%0,%1,%2,%3}, [%4];\n"
        : "=r"(r[0]), "=r"(r[1]), "=r"(r[2]), "=r"(r[3]) : "r"(addr));
}
__device__ __forceinline__ void ldsm_x4_t(unsigned r[4], unsigned addr) {
    asm volatile("ldmatrix.sync.aligned.m8n8.x4.trans.shared.b16 {%0,%1,%2,%3}, [%4];\n"
        : "=r"(r[0]), "=r"(r[1]), "=r"(r[2]), "=r"(r[3]) : "r"(addr));
}
__device__ __forceinline__ void mma16816(float c[4], const unsigned a[4], const unsigned b[2]) {
    asm volatile("mma.sync.aligned.m16n8k16.row.col.f32.bf16.bf16.f32 "
        "{%0,%1,%2,%3}, {%4,%5,%6,%7}, {%8,%9}, {%0,%1,%2,%3};\n"
        : "+f"(c[0]), "+f"(c[1]), "+f"(c[2]), "+f"(c[3])
        : "r"(a[0]), "r"(a[1]), "r"(a[2]), "r"(a[3]), "r"(b[0]), "r"(b[1]));
}

__device__ __forceinline__ float block_reduce_sum(float v, float* sbuf) {
    int tid = threadIdx.x;
    int lane = tid & 31, warp = tid >> 5;
    int nw = (blockDim.x + 31) >> 5;
    #pragma unroll
    for (int o = 16; o > 0; o >>= 1) v += __shfl_xor_sync(0xffffffffu, v, o);
    __syncthreads();
    if (lane == 0) sbuf[warp] = v;
    __syncthreads();
    if (warp == 0) {
        float w = (lane < nw) ? sbuf[lane] : 0.f;
        #pragma unroll
        for (int o = 16; o > 0; o >>= 1) w += __shfl_xor_sync(0xffffffffu, w, o);
        if (lane == 0) sbuf[0] = w;
    }
    __syncthreads();
    return sbuf[0];
}

__device__ __forceinline__ float gelu_exact(float x) {
    return 0.5f * x * (1.0f + erff(x * 0.70710678118654752f));
}

// ---------------- fp32 -> bf16 conversion -------------------------------------
__global__ void f2b_kernel(const float* __restrict__ in, __nv_bfloat16* __restrict__ out, int n)
{
    int stride = gridDim.x * blockDim.x * 4;
    for (int i = (blockIdx.x*blockDim.x + threadIdx.x)*4; i < n; i += stride) {
        float4 v = *(const float4*)(in + i);
        __nv_bfloat162* o = (__nv_bfloat162*)(out + i);
        o[0] = __floats2bfloat162_rn(v.x, v.y);
        o[1] = __floats2bfloat162_rn(v.z, v.w);
    }
}

// ---------------- embedding + layernorm (writes fp32 x and bf16 xb) ----------
__global__ void embed_ln_kernel(const float* __restrict__ wemb,
                                const float* __restrict__ pemb,
                                const float* __restrict__ g,
                                const float* __restrict__ bt,
                                const int*   __restrict__ ids,
                                float* __restrict__ x,
                                __nv_bfloat16* __restrict__ xb)
{
    int token = blockIdx.x;
    int s = token % Sc;
    int id = ids[token];
    __shared__ float buf[Hc];
    __shared__ float sbuf[32];
    float lsum = 0.f, lsum2 = 0.f;
    for (int c = threadIdx.x; c < Hc; c += blockDim.x) {
        float vv = wemb[(size_t)id*Hc + c] + pemb[(size_t)s*Hc + c];
        buf[c] = vv; lsum += vv; lsum2 += vv*vv;
    }
    float sum  = block_reduce_sum(lsum,  sbuf);
    float sum2 = block_reduce_sum(lsum2, sbuf);
    float mean = sum * (1.0f/Hc);
    float var  = sum2 * (1.0f/Hc) - mean*mean;
    float inv  = rsqrtf(var + 1e-12f);
    size_t base = (size_t)token*Hc;
    for (int c = threadIdx.x; c < Hc; c += blockDim.x) {
        float o = (buf[c] - mean) * inv * g[c] + bt[c];
        x[base + c] = o;
        xb[base + c] = __float2bfloat16(o);
    }
}

// ---------------- add-residual + layernorm ------------------------------------
__global__ void add_ln_kernel(float* __restrict__ x, const float* __restrict__ y,
                              const float* __restrict__ g, const float* __restrict__ bt,
                              __nv_bfloat16* __restrict__ xb)
{
    int token = blockIdx.x;
    __shared__ float buf[Hc];
    __shared__ float sbuf[32];
    size_t base = (size_t)token*Hc;
    float lsum = 0.f, lsum2 = 0.f;
    for (int c = threadIdx.x; c < Hc; c += blockDim.x) {
        float vv = x[base + c] + y[base + c];
        buf[c] = vv; lsum += vv; lsum2 += vv*vv;
    }
    float sum  = block_reduce_sum(lsum,  sbuf);
    float sum2 = block_reduce_sum(lsum2, sbuf);
    float mean = sum * (1.0f/Hc);
    float var  = sum2 * (1.0f/Hc) - mean*mean;
    float inv  = rsqrtf(var + 1e-12f);
    for (int c = threadIdx.x; c < Hc; c += blockDim.x) {
        float o = (buf[c] - mean) * inv * g[c] + bt[c];
        x[base + c] = o;
        xb[base + c] = __float2bfloat16(o);
    }
}

// ---------------- MMA GEMM: C = act(A @ W + bias) -----------------------------
// A: [M,K] bf16 row-major (lda), W: [K,N] bf16 row-major (ldb).
// Out fp32 (outf) or bf16 (outb), ldc. act=1 -> exact GELU.
// Tile 128x128x32, 256 threads (8 warps), warp tile 64x32.
#define LDA_S 40
#define LDB_S 136
__global__ __launch_bounds__(256) void gemm_mma(
    const __nv_bfloat16* __restrict__ A, int lda,
    const __nv_bfloat16* __restrict__ W, int ldb,
    const float* __restrict__ bias,
    float* __restrict__ outf, __nv_bfloat16* __restrict__ outb, int ldc,
    int K, int act)
{
    __shared__ __align__(16) __nv_bfloat16 As[2][128*LDA_S];
    __shared__ __align__(16) __nv_bfloat16 Bs[2][32*LDB_S];
    const int tid = threadIdx.x;
    const int lane = tid & 31, wid = tid >> 5;
    const int warp_m = wid & 1, warp_n = wid >> 1;
    const int m0 = blockIdx.y * 128, n0 = blockIdx.x * 128;

    const int ar = tid >> 2, ac = (tid & 3) * 8;
    const int br = tid >> 4, bc = (tid & 15) * 8;

    float acc[4][4][4];
    #pragma unroll
    for (int i = 0; i < 4; i++)
        #pragma unroll
        for (int j = 0; j < 4; j++)
            #pragma unroll
            for (int e = 0; e < 4; e++) acc[i][j][e] = 0.f;

    const int ktiles = K >> 5;

    // prefetch tile 0
    {
        const __nv_bfloat16* Ag = A + (size_t)(m0 + ar)*lda + ac;
        cp16(smem_u32(&As[0][ar*LDA_S + ac]), Ag);
        cp16(smem_u32(&As[0][(ar+64)*LDA_S + ac]), Ag + (size_t)64*lda);
        const __nv_bfloat16* Bg = W + (size_t)br*ldb + n0 + bc;
        cp16(smem_u32(&Bs[0][br*LDB_S + bc]), Bg);
        cp16(smem_u32(&Bs[0][(br+16)*LDB_S + bc]), Bg + (size_t)16*ldb);
    }
    cp_commit();

    for (int kt = 0; kt < ktiles; kt++) {
        if (kt + 1 < ktiles) {
            int nb = (kt + 1) & 1;
            const __nv_bfloat16* Ag = A + (size_t)(m0 + ar)*lda + (kt+1)*32 + ac;
            cp16(smem_u32(&As[nb][ar*LDA_S + ac]), Ag);
            cp16(smem_u32(&As[nb][(ar+64)*LDA_S + ac]), Ag + (size_t)64*lda);
            const __nv_bfloat16* Bg = W + (size_t)((kt+1)*32 + br)*ldb + n0 + bc;
            cp16(smem_u32(&Bs[nb][br*LDB_S + bc]), Bg);
            cp16(smem_u32(&Bs[nb][(br+16)*LDB_S + bc]), Bg + (size_t)16*ldb);
        }
        cp_commit();
        cp_wait<1>();
        __syncthreads();

        int buf = kt & 1;
        const unsigned asb = smem_u32(&As[buf][0]);
        const unsigned bsb = smem_u32(&Bs[buf][0]);
        #pragma unroll
        for (int kk = 0; kk < 2; kk++) {
            unsigned af[4][4];
            #pragma unroll
            for (int mt = 0; mt < 4; mt++) {
                int row = warp_m*64 + mt*16 + (lane & 15);
                int col = kk*16 + (lane >> 4) * 8;
                ldsm_x4(af[mt], asb + (row*LDA_S + col)*2);
            }
            unsigned bfr[4][2];
            #pragma unroll
            for (int nt2 = 0; nt2 < 2; nt2++) {
                int row = kk*16 + (lane & 15);
                int col = warp_n*32 + nt2*16 + (lane >> 4) * 8;
                unsigned r[4];
                ldsm_x4_t(r, bsb + (row*LDB_S + col)*2);
                bfr[nt2*2][0] = r[0]; bfr[nt2*2][1] = r[1];
                bfr[nt2*2+1][0] = r[2]; bfr[nt2*2+1][1] = r[3];
            }
            #pragma unroll
            for (int mt = 0; mt < 4; mt++)
                #pragma unroll
                for (int nt = 0; nt < 4; nt++)
                    mma16816(acc[mt][nt], af[mt], bfr[nt]);
        }
        __syncthreads();
    }

    // epilogue
    int orow = m0 + warp_m*64, ocol = n0 + warp_n*32;
    #pragma unroll
    for (int mt = 0; mt < 4; mt++) {
        int r = orow + mt*16 + (lane >> 2);
        #pragma unroll
        for (int nt = 0; nt < 4; nt++) {
            int c = ocol + nt*8 + (lane & 3)*2;
            float b0 = bias[c], b1 = bias[c+1];
            float v00 = acc[mt][nt][0] + b0, v01 = acc[mt][nt][1] + b1;
            float v10 = acc[mt][nt][2] + b0, v11 = acc[mt][nt][3] + b1;
            if (act) {
                v00 = gelu_exact(v00); v01 = gelu_exact(v01);
                v10 = gelu_exact(v10); v11 = gelu_exact(v11);
            }
            if (outf) {
                *(float2*)&outf[(size_t)r*ldc + c]     = make_float2(v00, v01);
                *(float2*)&outf[(size_t)(r+8)*ldc + c] = make_float2(v10, v11);
            } else {
                *(__nv_bfloat162*)&outb[(size_t)r*ldc + c]     = __floats2bfloat162_rn(v00, v01);
                *(__nv_bfloat162*)&outb[(size_t)(r+8)*ldc + c] = __floats2bfloat162_rn(v10, v11);
            }
        }
    }
}

// ---------------- attention scores: sc = (Q . K^T)/8 (per bh, 128x128 tiles) --
__global__ __launch_bounds__(256) void attn_scores_mma(
    const __nv_bfloat16* __restrict__ q,
    const __nv_bfloat16* __restrict__ k,
    float* __restrict__ sc)
{
    __shared__ __align__(16) __nv_bfloat16 Qs[128*72];
    __shared__ __align__(16) __nv_bfloat16 Ks[128*72];
    const int tid = threadIdx.x;
    const int lane = tid & 31, wid = tid >> 5;
    const int warp_m = wid & 1, warp_n = wid >> 1;
    int bh = blockIdx.z, b = bh / NHc, h = bh % NHc;
    int i0 = blockIdx.y*128, j0 = blockIdx.x*128;
    const __nv_bfloat16* qb = q + ((size_t)b*Sc + i0)*Hc + h*DHc;
    const __nv_bfloat16* kb = k + ((size_t)b*Sc + j0)*Hc + h*DHc;

    int lr = tid >> 1, lc = (tid & 1) * 32;
    #pragma unroll
    for (int cch = 0; cch < 4; cch++) {
        cp16(smem_u32(&Qs[lr*72 + lc + cch*8]), qb + (size_t)lr*Hc + lc + cch*8);
        cp16(smem_u32(&Ks[lr*72 + lc + cch*8]), kb + (size_t)lr*Hc + lc + cch*8);
    }
    cp_commit();
    cp_wait<0>();
    __syncthreads();

    float acc[4][4][4];
    #pragma unroll
    for (int i = 0; i < 4; i++)
        #pragma unroll
        for (int j = 0; j < 4; j++)
            #pragma unroll
            for (int e = 0; e < 4; e++) acc[i][j][e] = 0.f;

    const unsigned qsb = smem_u32(Qs), ksb = smem_u32(Ks);
    #pragma unroll
    for (int kk = 0; kk < 4; kk++) {
        unsigned af[4][4];
        #pragma unroll
        for (int mt = 0; mt < 4; mt++) {
            int row = warp_m*64 + mt*16 + (lane & 15);
            int col = kk*16 + (lane >> 4) * 8;
            ldsm_x4(af[mt], qsb + (row*72 + col)*2);
        }
        unsigned bfr[4][2];
        #pragma unroll
        for (int nt2 = 0; nt2 < 2; nt2++) {
            // K stored [token][d] (n-major): non-trans ldmatrix gives B frags
            int row = warp_n*32 + nt2*16 + (lane & 7) + ((lane >> 4) << 3);
            int col = kk*16 + ((lane >> 3) & 1) * 8;
            unsigned r[4];
            ldsm_x4(r, ksb + (row*72 + col)*2);
            bfr[nt2*2][0] = r[0]; bfr[nt2*2][1] = r[1];
            bfr[nt2*2+1][0] = r[2]; bfr[nt2*2+1][1] = r[3];
        }
        #pragma unroll
        for (int mt = 0; mt < 4; mt++)
            #pragma unroll
            for (int nt = 0; nt < 4; nt++)
                mma16816(acc[mt][nt], af[mt], bfr[nt]);
    }

    float* scb = sc + (size_t)bh*Sc*Sc;
    #pragma unroll
    for (int mt = 0; mt < 4; mt++) {
        int r = i0 + warp_m*64 + mt*16 + (lane >> 2);
        #pragma unroll
        for (int nt = 0; nt < 4; nt++) {
            int c = j0 + warp_n*32 + nt*8 + (lane & 3)*2;
            *(float2*)&scb[(size_t)r*Sc + c]     = make_float2(acc[mt][nt][0]*0.125f, acc[mt][nt][1]*0.125f);
            *(float2*)&scb[(size_t)(r+8)*Sc + c] = make_float2(acc[mt][nt][2]*0.125f, acc[mt][nt][3]*0.125f);
        }
    }
}

// ---------------- masked softmax: fp32 scores -> bf16 probs -------------------
__global__ __launch_bounds__(128) void softmax_kernel(const float* __restrict__ sc,
                                                      const int* __restrict__ amask,
                                                      __nv_bfloat16* __restrict__ pb)
{
    unsigned int row = blockIdx.x;
    int b = (int)(row / Sc) / NHc;
    const float* p = sc + (size_t)row * Sc;
    __nv_bfloat16* po = pb + (size_t)row * Sc;
    const int* mrow = amask + (size_t)b * Sc;
    int tid = threadIdx.x;

    const float NEG = -3.4028234663852886e+38f;
    float4 vv = ((const float4*)p)[tid];
    int4  mm = ((const int4*)mrow)[tid];
    float v0 = mm.x ? vv.x : NEG;
    float v1 = mm.y ? vv.y : NEG;
    float v2 = mm.z ? vv.z : NEG;
    float v3 = mm.w ? vv.w : NEG;

    __shared__ float sred[32];
    __shared__ float s_stat;
    int lane = tid & 31, warp = tid >> 5;

    float mx = fmaxf(fmaxf(v0, v1), fmaxf(v2, v3));
    #pragma unroll
    for (int o = 16; o > 0; o >>= 1) mx = fmaxf(mx, __shfl_xor_sync(0xffffffffu, mx, o));
    if (lane == 0) sred[warp] = mx;
    __syncthreads();
    if (tid == 0) {
        float m = sred[0];
        for (int w = 1; w < 4; w++) m = fmaxf(m, sred[w]);
        s_stat = m;
    }
    __syncthreads();
    float M = s_stat;

    float e0 = expf(v0 - M), e1 = expf(v1 - M), e2 = expf(v2 - M), e3 = expf(v3 - M);
    float sm = e0 + e1 + e2 + e3;
    #pragma unroll
    for (int o = 16; o > 0; o >>= 1) sm += __shfl_xor_sync(0xffffffffu, sm, o);
    __syncthreads();
    if (lane == 0) sred[warp] = sm;
    __syncthreads();
    if (tid == 0) s_stat = sred[0] + sred[1] + sred[2] + sred[3];
    __syncthreads();
    float inv = 1.0f / s_stat;

    __nv_bfloat162* o2 = (__nv_bfloat162*)(po + tid*4);
    o2[0] = __floats2bfloat162_rn(e0*inv, e1*inv);
    o2[1] = __floats2bfloat162_rn(e2*inv, e3*inv);
}

// ---------------- ctx = probs @ V (bf16 mma, per bh 128x64) -------------------
__global__ __launch_bounds__(128) void attn_ctx_mma(
    const __nv_bfloat16* __restrict__ pb,
    const __nv_bfloat16* __restrict__ v,
    __nv_bfloat16* __restrict__ ctx)
{
    __shared__ __align__(16) __nv_bfloat16 Ps[2][128*LDA_S];
    __shared__ __align__(16) __nv_bfloat16 Vs[2][32*72];
    const int tid = threadIdx.x;
    const int lane = tid & 31, wid = tid >> 5;
    const int warp_m = wid & 1, warp_n = wid >> 1;  // 4 warps: 2x2
    int bh = blockIdx.y, b = bh / NHc, h = bh % NHc;
    int i0 = blockIdx.x * 128;
    const __nv_bfloat16* Pg = pb + ((size_t)bh*Sc + i0)*Sc;
    const __nv_bfloat16* vb = v + (size_t)b*Sc*Hc + h*DHc;

    float acc[4][4][4];
    #pragma unroll
    for (int i = 0; i < 4; i++)
        #pragma unroll
        for (int j = 0; j < 4; j++)
            #pragma unroll
            for (int e = 0; e < 4; e++) acc[i][j][e] = 0.f;

    const int vr = tid >> 2, vc = (tid & 3) * 16;

    // prefetch tile 0
    {
        #pragma unroll
        for (int c = 0; c < 4; c++)
            cp16(smem_u32(&Ps[0][tid*LDA_S + c*8]), Pg + (size_t)tid*Sc + c*8);
        cp16(smem_u32(&Vs[0][vr*72 + vc]),     vb + (size_t)vr*Hc + vc);
        cp16(smem_u32(&Vs[0][vr*72 + vc + 8]), vb + (size_t)vr*Hc + vc + 8);
    }
    cp_commit();

    const int ktiles = Sc / 32;  // 16
    for (int kt = 0; kt < ktiles; kt++) {
        if (kt + 1 < ktiles) {
            int nb = (kt + 1) & 1;
            #pragma unroll
            for (int c = 0; c < 4; c++)
                cp16(smem_u32(&Ps[nb][tid*LDA_S + c*8]), Pg + (size_t)tid*Sc + (kt+1)*32 + c*8);
            const __nv_bfloat16* vg = vb + (size_t)((kt+1)*32 + vr)*Hc + vc;
            cp16(smem_u32(&Vs[nb][vr*72 + vc]),     vg);
            cp16(smem_u32(&Vs[nb][vr*72 + vc + 8]), vg + 8);
        }
        cp_commit();
        cp_wait<1>();
        __syncthreads();

        int buf = kt & 1;
        const unsigned psb = smem_u32(&Ps[buf][0]);
        const unsigned vsb = smem_u32(&Vs[buf][0]);
        #pragma unroll
        for (int kk = 0; kk < 2; kk++) {
            unsigned af[4][4];
            #pragma unroll
            for (int mt = 0; mt < 4; mt++) {
                int row = warp_m*64 + mt*16 + (lane & 15);
                int col = kk*16 + (lane >> 4) * 8;
                ldsm_x4(af[mt], psb + (row*LDA_S + col)*2);
            }
            unsigned bfr[4][2];
            #pragma unroll
            for (int nt2 = 0; nt2 < 2; nt2++) {
                int row = kk*16 + (lane & 15);
                int col = warp_n*32 + nt2*16 + (lane >> 4) * 8;
                unsigned r[4];
                ldsm_x4_t(r, vsb + (row*72 + col)*2);
                bfr[nt2*2][0] = r[0]; bfr[nt2*2][1] = r[1];
                bfr[nt2*2+1][0] = r[2]; bfr[nt2*2+1][1] = r[3];
            }
            #pragma unroll
            for (int mt = 0; mt < 4; mt++)
                #pragma unroll
                for (int nt = 0; nt < 4; nt++)
                    mma16816(acc[mt][nt], af[mt], bfr[nt]);
        }
        __syncthreads();
    }

    #pragma unroll
    for (int mt = 0; mt < 4; mt++) {
        int r = i0 + warp_m*64 + mt*16 + (lane >> 2);
        #pragma unroll
        for (int nt = 0; nt < 4; nt++) {
            int c = warp_n*32 + nt*8 + (lane & 3)*2;
            __nv_bfloat16* o0 = &ctx[((size_t)b*Sc + r)*Hc + h*DHc + c];
            __nv_bfloat16* o1 = &ctx[((size_t)b*Sc + r + 8)*Hc + h*DHc + c];
            *(__nv_bfloat162*)o0 = __floats2bfloat162_rn(acc[mt][nt][0], acc[mt][nt][1]);
            *(__nv_bfloat162*)o1 = __floats2bfloat162_rn(acc[mt][nt][2], acc[mt][nt][3]);
        }
    }
}

// ---------------- emissions = x @ cls_w + cls_b (T=7, fp32) -------------------
__global__ void emissions_kernel(const float* __restrict__ x,
                                 const float* __restrict__ cw,
                                 const float* __restrict__ cb,
                                 float* __restrict__ em)
{
    int token = blockIdx.x;
    int w = threadIdx.x >> 5, lane = threadIdx.x & 31;
    const float* xr = x + (size_t)token*Hc;
    float sum = 0.f;
    for (int c = lane; c < Hc; c += 32) sum += xr[c] * cw[(size_t)c*Tc + w];
    #pragma unroll
    for (int o = 16; o > 0; o >>= 1) sum += __shfl_down_sync(0xffffffffu, sum, o);
    if (lane == 0) em[(size_t)token*Tc + w] = sum + cb[w];
}

// ---------------- CRF ----------------------------------------------------------
__global__ void crf_kernel(const float* __restrict__ em,
                           const int*   __restrict__ labels,
                           const float* __restrict__ cstart,
                           const float* __restrict__ cend,
                           const float* __restrict__ ctrans,
                           float* __restrict__ num_out,
                           float* __restrict__ den_out)
{
    __shared__ float tr[Tc*Tc];
    __shared__ float sbuf[32];
    __shared__ int   s_len;
    int b = blockIdx.x, tid = threadIdx.x;
    const int* lab = labels + (size_t)b*Sc;
    const float* e = em + (size_t)b*Sc*Tc;
    if (tid < Tc*Tc) tr[tid] = ctrans[tid];
    __syncthreads();

    float cnt = 0.f, part = 0.f;
    for (int t = tid; t < Sc; t += blockDim.x) {
        bool m = (t == 0) || (lab[t] != -100);
        if (m) cnt += 1.f;
        if (t >= 1 && lab[t] != -100) {
            int cur = lab[t];
            int prv;
            if (t - 1 == 0) { prv = lab[0]; prv = prv < 0 ? 0 : (prv > Tc-1 ? Tc-1 : prv); }
            else            { prv = lab[t-1]; if (prv == -100) prv = 0; }
            part += tr[prv*Tc + cur] + e[(size_t)t*Tc + cur];
        }
    }
    float totc = block_reduce_sum(cnt, sbuf);
    float tot  = block_reduce_sum(part, sbuf);
    if (tid == 0) {
        int len = (int)(totc + 0.5f);
        s_len = len;
        int s0 = lab[0]; s0 = s0 < 0 ? 0 : (s0 > Tc-1 ? Tc-1 : s0);
        float num = cstart[s0] + e[s0] + tot;
        int send = len - 1;
        int sl;
        if (send == 0) sl = s0;
        else { sl = lab[send]; if (sl == -100) sl = 0; }
        num += cend[sl];
        num_out[b] = num;
    }
    __syncthreads();
    int len = s_len;

    if (tid < 32) {
        int j = tid;
        int jj = (j < Tc) ? j : 0;
        float a = cstart[jj] + e[jj];
        for (int t = 1; t < len; t++) {
            float ej = e[(size_t)t*Tc + jj];
            float av[Tc];
            float m = -3.4028235e+38f;
            #pragma unroll
            for (int i = 0; i < Tc; i++) {
                float ai = __shfl_sync(0xffffffffu, a, i);
                float vv = ai + tr[i*Tc + jj];
                av[i] = vv; m = fmaxf(m, vv);
            }
            float ss = 0.f;
            #pragma unroll
            for (int i = 0; i < Tc; i++) ss += expf(av[i] - m);
            float ne = m + logf(ss) + ej;
            a = (j < Tc) ? ne : a;
        }
        float fa = (j < Tc) ? a + cend[jj] : -3.4028235e+38f;
        float mm = fa;
        #pragma unroll
        for (int o = 16; o > 0; o >>= 1) mm = fmaxf(mm, __shfl_xor_sync(0xffffffffu, mm, o));
        float es = (j < Tc) ? expf(fa - mm) : 0.f;
        #pragma unroll
        for (int o = 16; o > 0; o >>= 1) es += __shfl_xor_sync(0xffffffffu, es, o);
        if (tid == 0) den_out[b] = mm + logf(es);
    }
}

// ---------------- final loss ---------------------------------------------------
__global__ void loss_kernel(const float* __restrict__ num,
                            const float* __restrict__ den,
                            float* __restrict__ out)
{
    int tid = threadIdx.x;
    float v = (tid < Bc) ? (num[tid] - den[tid]) : 0.f;
    #pragma unroll
    for (int o = 16; o > 0; o >>= 1) v += __shfl_down_sync(0xffffffffu, v, o);
    if (tid == 0) out[0] = -v / (float)Bc;
}

// ---------------- host launcher ------------------------------------------------
extern "C" void kernel_launch(void* const* d_in, const int* in_sizes, int n_in,
                              void* d_out, int out_size)
{
    const float* word_emb = (const float*)d_in[0];
    const float* pos_emb  = (const float*)d_in[1];
    const float* emb_ln_s = (const float*)d_in[2];
    const float* emb_ln_b = (const float*)d_in[3];
    const float* attn_qw  = (const float*)d_in[4];
    const float* attn_qb  = (const float*)d_in[5];
    const float* attn_kw  = (const float*)d_in[6];
    const float* attn_kb  = (const float*)d_in[7];
    const float* attn_vw  = (const float*)d_in[8];
    const float* attn_vb  = (const float*)d_in[9];
    const float* attn_ow  = (const float*)d_in[10];
    const float* attn_ob  = (const float*)d_in[11];
    const float* ln1_s    = (const float*)d_in[12];
    const float* ln1_b    = (const float*)d_in[13];
    const float* ffn_w1   = (const float*)d_in[14];
    const float* ffn_b1   = (const float*)d_in[15];
    const float* ffn_w2   = (const float*)d_in[16];
    const float* ffn_b2   = (const float*)d_in[17];
    const float* ln2_s    = (const float*)d_in[18];
    const float* ln2_b    = (const float*)d_in[19];
    const float* cls_w    = (const float*)d_in[20];
    const float* cls_b    = (const float*)d_in[21];
    const float* crf_start= (const float*)d_in[22];
    const float* crf_end  = (const float*)d_in[23];
    const float* crf_trans= (const float*)d_in[24];
    const int* input_ids  = (const int*)d_in[25];
    const int* amask      = (const int*)d_in[26];
    const int* labels     = (const int*)d_in[27];

    float *x, *y, *sc, *em, *nb, *db;
    __nv_bfloat16 *xb, *q, *k, *v, *ctx, *pbuf, *hb, *wb;
    cudaGetSymbolAddress((void**)&x,    g_x);
    cudaGetSymbolAddress((void**)&xb,   g_xb);
    cudaGetSymbolAddress((void**)&y,    g_y);
    cudaGetSymbolAddress((void**)&q,    g_q);
    cudaGetSymbolAddress((void**)&k,    g_k);
    cudaGetSymbolAddress((void**)&v,    g_v);
    cudaGetSymbolAddress((void**)&ctx,  g_ctx);
    cudaGetSymbolAddress((void**)&sc,   g_sc);
    cudaGetSymbolAddress((void**)&pbuf, g_pb);
    cudaGetSymbolAddress((void**)&hb,   g_h);
    cudaGetSymbolAddress((void**)&wb,   g_wb);
    cudaGetSymbolAddress((void**)&em,   g_em);
    cudaGetSymbolAddress((void**)&nb,   g_num);
    cudaGetSymbolAddress((void**)&db,   g_den);

    // bf16 weight copies
    const size_t HH = (size_t)Lc*Hc*Hc;       // 3538944
    const size_t HF = (size_t)Lc*Hc*FFc;      // 14155776
    __nv_bfloat16* wq = wb;
    __nv_bfloat16* wk = wb + HH;
    __nv_bfloat16* wv = wb + 2*HH;
    __nv_bfloat16* wo = wb + 3*HH;
    __nv_bfloat16* w1 = wb + 4*HH;
    __nv_bfloat16* w2 = wb + 4*HH + HF;
    f2b_kernel<<<2048, 256>>>(attn_qw, wq, (int)HH);
    f2b_kernel<<<2048, 256>>>(attn_kw, wk, (int)HH);
    f2b_kernel<<<2048, 256>>>(attn_vw, wv, (int)HH);
    f2b_kernel<<<2048, 256>>>(attn_ow, wo, (int)HH);
    f2b_kernel<<<4096, 256>>>(ffn_w1, w1, (int)HF);
    f2b_kernel<<<4096, 256>>>(ffn_w2, w2, (int)HF);

    embed_ln_kernel<<<BSc, 256>>>(word_emb, pos_emb, emb_ln_s, emb_ln_b, input_ids, x, xb);

    dim3 gHH(Hc/128, BSc/128);
    for (int i = 0; i < Lc; i++) {
        size_t wOff = (size_t)i*Hc*Hc, bOff = (size_t)i*Hc;
        gemm_mma<<<gHH, 256>>>(xb, Hc, wq + wOff, Hc, attn_qb + bOff, nullptr, q, Hc, Hc, 0);
        gemm_mma<<<gHH, 256>>>(xb, Hc, wk + wOff, Hc, attn_kb + bOff, nullptr, k, Hc, Hc, 0);
        gemm_mma<<<gHH, 256>>>(xb, Hc, wv + wOff, Hc, attn_vb + bOff, nullptr, v, Hc, Hc, 0);

        attn_scores_mma<<<dim3(Sc/128, Sc/128, Bc*NHc), 256>>>(q, k, sc);
        softmax_kernel<<<Bc*NHc*Sc, 128>>>(sc, amask, pbuf);
        attn_ctx_mma<<<dim3(Sc/128, Bc*NHc), 128>>>(pbuf, v, ctx);

        gemm_mma<<<gHH, 256>>>(ctx, Hc, wo + wOff, Hc, attn_ob + bOff, y, nullptr, Hc, Hc, 0);
        add_ln_kernel<<<BSc, 256>>>(x, y, ln1_s + bOff, ln1_b + bOff, xb);

        gemm_mma<<<dim3(FFc/128, BSc/128), 256>>>(xb, Hc, w1 + (size_t)i*Hc*FFc, FFc,
                                                  ffn_b1 + (size_t)i*FFc, nullptr, hb, FFc, Hc, 1);
        gemm_mma<<<gHH, 256>>>(hb, FFc, w2 + (size_t)i*FFc*Hc, Hc,
                               ffn_b2 + bOff, y, nullptr, Hc, FFc, 0);
        add_ln_kernel<<<BSc, 256>>>(x, y, ln2_s + bOff, ln2_b + bOff, xb);
    }

    emissions_kernel<<<BSc, 224>>>(x, cls_w, cls_b, em);
    crf_kernel<<<Bc, 256>>>(em, labels, crf_start, crf_end, crf_trans, nb, db);
    loss_kernel<<<1, 32>>>(nb, db, (float*)d_out);
}

// round 3
// speedup vs baseline: 5.8525x; 1.0844x over previous
#include <cuda_runtime.h>
#include <cuda_bf16.h>
#include <math.h>

// Problem constants
#define Bc 32
#define Sc 512
#define Hc 768
#define Lc 6
#define NHc 12
#define FFc 3072
#define Tc 7
#define DHc 64
#define BSc (Bc*Sc)          // 16384
#define QKVN (3*Hc)          // 2304

// ---------------- scratch buffers (device globals; no allocation allowed) ----
__device__ float          g_x  [(size_t)BSc*Hc];        // fp32 residual stream
__device__ __nv_bfloat16  g_xb [(size_t)BSc*Hc];        // bf16 copy for GEMM input
__device__ float          g_y  [(size_t)BSc*Hc];        // fp32 projection output
__device__ __nv_bfloat16  g_qkv[(size_t)BSc*QKVN];      // fused qkv output
__device__ __nv_bfloat16  g_ctx[(size_t)BSc*Hc];
__device__ __nv_bfloat16  g_h  [(size_t)BSc*FFc];       // bf16 FFN hidden
__device__ __nv_bfloat16  g_wb [(size_t)(4*Lc*Hc*Hc + 2*Lc*Hc*FFc)]; // bf16 weights
__device__ float          g_bqkv[(size_t)Lc*QKVN];      // packed qkv bias
__device__ float          g_em [(size_t)BSc*Tc];
__device__ float          g_num[Bc];
__device__ float          g_den[Bc];

// ---------------- PTX helpers -------------------------------------------------
__device__ __forceinline__ unsigned smem_u32(const void* p) {
    return (unsigned)__cvta_generic_to_shared(p);
}
__device__ __forceinline__ void cp16(unsigned saddr, const void* g) {
    asm volatile("cp.async.cg.shared.global [%0], [%1], 16;\n" :: "r"(saddr), "l"(g));
}
__device__ __forceinline__ void cp_commit() {
    asm volatile("cp.async.commit_group;\n");
}
template<int N>
__device__ __forceinline__ void cp_wait() {
    asm volatile("cp.async.wait_group %0;\n" :: "n"(N));
}
__device__ __forceinline__ void ldsm_x4(unsigned r[4], unsigned addr) {
    asm volatile("ldmatrix.sync.aligned.m8n8.x4.shared.b16 {%0,%1,%2,%3}, [%4];\n"
        : "=r"(r[0]), "=r"(r[1]), "=r"(r[2]), "=r"(r[3]) : "r"(addr));
}
__device__ __forceinline__ void ldsm_x4_t(unsigned r[4], unsigned addr) {
    asm volatile("ldmatrix.sync.aligned.m8n8.x4.trans.shared.b16 {%0,%1,%2,%3}, [%4];\n"
        : "=r"(r[0]), "=r"(r[1]), "=r"(r[2]), "=r"(r[3]) : "r"(addr));
}
__device__ __forceinline__ void mma16816(float c[4], const unsigned a[4], const unsigned b[2]) {
    asm volatile("mma.sync.aligned.m16n8k16.row.col.f32.bf16.bf16.f32 "
        "{%0,%1,%2,%3}, {%4,%5,%6,%7}, {%8,%9}, {%0,%1,%2,%3};\n"
        : "+f"(c[0]), "+f"(c[1]), "+f"(c[2]), "+f"(c[3])
        : "r"(a[0]), "r"(a[1]), "r"(a[2]), "r"(a[3]), "r"(b[0]), "r"(b[1]));
}
__device__ __forceinline__ unsigned packbf2(float a, float b) {
    __nv_bfloat162 t = __floats2bfloat162_rn(a, b);
    return *(unsigned*)&t;
}

__device__ __forceinline__ float block_reduce_sum(float v, float* sbuf) {
    int tid = threadIdx.x;
    int lane = tid & 31, warp = tid >> 5;
    int nw = (blockDim.x + 31) >> 5;
    #pragma unroll
    for (int o = 16; o > 0; o >>= 1) v += __shfl_xor_sync(0xffffffffu, v, o);
    __syncthreads();
    if (lane == 0) sbuf[warp] = v;
    __syncthreads();
    if (warp == 0) {
        float w = (lane < nw) ? sbuf[lane] : 0.f;
        #pragma unroll
        for (int o = 16; o > 0; o >>= 1) w += __shfl_xor_sync(0xffffffffu, w, o);
        if (lane == 0) sbuf[0] = w;
    }
    __syncthreads();
    return sbuf[0];
}

__device__ __forceinline__ float gelu_exact(float x) {
    return 0.5f * x * (1.0f + erff(x * 0.70710678118654752f));
}

// ---------------- fp32 -> bf16 conversion -------------------------------------
__global__ void f2b_kernel(const float* __restrict__ in, __nv_bfloat16* __restrict__ out, int n)
{
    int stride = gridDim.x * blockDim.x * 4;
    for (int i = (blockIdx.x*blockDim.x + threadIdx.x)*4; i < n; i += stride) {
        float4 v = *(const float4*)(in + i);
        __nv_bfloat162* o = (__nv_bfloat162*)(out + i);
        o[0] = __floats2bfloat162_rn(v.x, v.y);
        o[1] = __floats2bfloat162_rn(v.z, v.w);
    }
}

// ---------------- pack fused QKV weights/biases --------------------------------
__global__ void pack_qkv_w(const float* __restrict__ qw, const float* __restrict__ kw,
                           const float* __restrict__ vw, __nv_bfloat16* __restrict__ out)
{
    const size_t total = (size_t)Lc*Hc*QKVN;
    size_t stride = (size_t)gridDim.x * blockDim.x * 2;
    for (size_t i = ((size_t)blockIdx.x*blockDim.x + threadIdx.x)*2; i < total; i += stride) {
        size_t lk = i / QKVN;
        int n = (int)(i % QKVN);
        const float* src; int nn;
        if (n < Hc)        { src = qw; nn = n; }
        else if (n < 2*Hc) { src = kw; nn = n - Hc; }
        else               { src = vw; nn = n - 2*Hc; }
        size_t soff = lk*Hc + nn;
        *(__nv_bfloat162*)(out + i) = __floats2bfloat162_rn(src[soff], src[soff+1]);
    }
}
__global__ void pack_qkv_b(const float* __restrict__ qb, const float* __restrict__ kb,
                           const float* __restrict__ vb, float* __restrict__ out)
{
    int i = blockIdx.x*blockDim.x + threadIdx.x;
    if (i >= Lc*QKVN) return;
    int l = i / QKVN, n = i % QKVN;
    float v;
    if (n < Hc)        v = qb[l*Hc + n];
    else if (n < 2*Hc) v = kb[l*Hc + n - Hc];
    else               v = vb[l*Hc + n - 2*Hc];
    out[i] = v;
}

// ---------------- embedding + layernorm (writes fp32 x and bf16 xb) ----------
__global__ void embed_ln_kernel(const float* __restrict__ wemb,
                                const float* __restrict__ pemb,
                                const float* __restrict__ g,
                                const float* __restrict__ bt,
                                const int*   __restrict__ ids,
                                float* __restrict__ x,
                                __nv_bfloat16* __restrict__ xb)
{
    int token = blockIdx.x;
    int s = token % Sc;
    int id = ids[token];
    __shared__ float buf[Hc];
    __shared__ float sbuf[32];
    float lsum = 0.f, lsum2 = 0.f;
    for (int c = threadIdx.x; c < Hc; c += blockDim.x) {
        float vv = wemb[(size_t)id*Hc + c] + pemb[(size_t)s*Hc + c];
        buf[c] = vv; lsum += vv; lsum2 += vv*vv;
    }
    float sum  = block_reduce_sum(lsum,  sbuf);
    float sum2 = block_reduce_sum(lsum2, sbuf);
    float mean = sum * (1.0f/Hc);
    float var  = sum2 * (1.0f/Hc) - mean*mean;
    float inv  = rsqrtf(var + 1e-12f);
    size_t base = (size_t)token*Hc;
    for (int c = threadIdx.x; c < Hc; c += blockDim.x) {
        float o = (buf[c] - mean) * inv * g[c] + bt[c];
        x[base + c] = o;
        xb[base + c] = __float2bfloat16(o);
    }
}

// ---------------- add-residual + layernorm ------------------------------------
__global__ void add_ln_kernel(float* __restrict__ x, const float* __restrict__ y,
                              const float* __restrict__ g, const float* __restrict__ bt,
                              __nv_bfloat16* __restrict__ xb)
{
    int token = blockIdx.x;
    __shared__ float buf[Hc];
    __shared__ float sbuf[32];
    size_t base = (size_t)token*Hc;
    float lsum = 0.f, lsum2 = 0.f;
    for (int c = threadIdx.x; c < Hc; c += blockDim.x) {
        float vv = x[base + c] + y[base + c];
        buf[c] = vv; lsum += vv; lsum2 += vv*vv;
    }
    float sum  = block_reduce_sum(lsum,  sbuf);
    float sum2 = block_reduce_sum(lsum2, sbuf);
    float mean = sum * (1.0f/Hc);
    float var  = sum2 * (1.0f/Hc) - mean*mean;
    float inv  = rsqrtf(var + 1e-12f);
    for (int c = threadIdx.x; c < Hc; c += blockDim.x) {
        float o = (buf[c] - mean) * inv * g[c] + bt[c];
        x[base + c] = o;
        xb[base + c] = __float2bfloat16(o);
    }
}

// ---------------- MMA GEMM (4-stage pipeline): C = act(A @ W + bias) ----------
#define LDA_S 40
#define LDB_S 136
#define STAGES 4
#define GEMM_SMEM (STAGES*(128*LDA_S + 32*LDB_S)*2)

__global__ __launch_bounds__(256) void gemm_mma(
    const __nv_bfloat16* __restrict__ A, int lda,
    const __nv_bfloat16* __restrict__ W, int ldb,
    const float* __restrict__ bias,
    float* __restrict__ outf, __nv_bfloat16* __restrict__ outb, int ldc,
    int K, int act)
{
    extern __shared__ char smx[];
    __nv_bfloat16* As = (__nv_bfloat16*)smx;             // STAGES*128*LDA_S
    __nv_bfloat16* Bs = As + STAGES*128*LDA_S;           // STAGES*32*LDB_S
    const int tid = threadIdx.x;
    const int lane = tid & 31, wid = tid >> 5;
    const int warp_m = wid & 1, warp_n = wid >> 1;
    const int m0 = blockIdx.y * 128, n0 = blockIdx.x * 128;

    const int ar = tid >> 2, ac = (tid & 3) * 8;
    const int br = tid >> 4, bc = (tid & 15) * 8;
    const int ktiles = K >> 5;

    float acc[4][4][4];
    #pragma unroll
    for (int i = 0; i < 4; i++)
        #pragma unroll
        for (int j = 0; j < 4; j++)
            #pragma unroll
            for (int e = 0; e < 4; e++) acc[i][j][e] = 0.f;

    auto issue = [&](int stage, int kt) {
        __nv_bfloat16* as = As + stage*128*LDA_S;
        __nv_bfloat16* bs = Bs + stage*32*LDB_S;
        const __nv_bfloat16* Ag = A + (size_t)(m0 + ar)*lda + kt*32 + ac;
        cp16(smem_u32(as + ar*LDA_S + ac), Ag);
        cp16(smem_u32(as + (ar+64)*LDA_S + ac), Ag + (size_t)64*lda);
        const __nv_bfloat16* Bg = W + (size_t)(kt*32 + br)*ldb + n0 + bc;
        cp16(smem_u32(bs + br*LDB_S + bc), Bg);
        cp16(smem_u32(bs + (br+16)*LDB_S + bc), Bg + (size_t)16*ldb);
    };

    // prologue: stages 0..STAGES-2
    #pragma unroll
    for (int s = 0; s < STAGES-1; s++) {
        if (s < ktiles) issue(s, s);
        cp_commit();
    }

    for (int kt = 0; kt < ktiles; kt++) {
        cp_wait<STAGES-2>();
        __syncthreads();
        if (kt + STAGES-1 < ktiles) issue((kt + STAGES-1) % STAGES, kt + STAGES-1);
        cp_commit();

        int stage = kt % STAGES;
        const unsigned asb = smem_u32(As + stage*128*LDA_S);
        const unsigned bsb = smem_u32(Bs + stage*32*LDB_S);
        #pragma unroll
        for (int kk = 0; kk < 2; kk++) {
            unsigned af[4][4];
            #pragma unroll
            for (int mt = 0; mt < 4; mt++) {
                int row = warp_m*64 + mt*16 + (lane & 15);
                int col = kk*16 + (lane >> 4) * 8;
                ldsm_x4(af[mt], asb + (row*LDA_S + col)*2);
            }
            unsigned bfr[4][2];
            #pragma unroll
            for (int nt2 = 0; nt2 < 2; nt2++) {
                int row = kk*16 + (lane & 15);
                int col = warp_n*32 + nt2*16 + (lane >> 4) * 8;
                unsigned r[4];
                ldsm_x4_t(r, bsb + (row*LDB_S + col)*2);
                bfr[nt2*2][0] = r[0]; bfr[nt2*2][1] = r[1];
                bfr[nt2*2+1][0] = r[2]; bfr[nt2*2+1][1] = r[3];
            }
            #pragma unroll
            for (int mt = 0; mt < 4; mt++)
                #pragma unroll
                for (int nt = 0; nt < 4; nt++)
                    mma16816(acc[mt][nt], af[mt], bfr[nt]);
        }
    }

    // epilogue
    int orow = m0 + warp_m*64, ocol = n0 + warp_n*32;
    #pragma unroll
    for (int mt = 0; mt < 4; mt++) {
        int r = orow + mt*16 + (lane >> 2);
        #pragma unroll
        for (int nt = 0; nt < 4; nt++) {
            int c = ocol + nt*8 + (lane & 3)*2;
            float b0 = bias[c], b1 = bias[c+1];
            float v00 = acc[mt][nt][0] + b0, v01 = acc[mt][nt][1] + b1;
            float v10 = acc[mt][nt][2] + b0, v11 = acc[mt][nt][3] + b1;
            if (act) {
                v00 = gelu_exact(v00); v01 = gelu_exact(v01);
                v10 = gelu_exact(v10); v11 = gelu_exact(v11);
            }
            if (outf) {
                *(float2*)&outf[(size_t)r*ldc + c]     = make_float2(v00, v01);
                *(float2*)&outf[(size_t)(r+8)*ldc + c] = make_float2(v10, v11);
            } else {
                *(__nv_bfloat162*)&outb[(size_t)r*ldc + c]     = __floats2bfloat162_rn(v00, v01);
                *(__nv_bfloat162*)&outb[(size_t)(r+8)*ldc + c] = __floats2bfloat162_rn(v10, v11);
            }
        }
    }
}

// ---------------- fused flash attention ---------------------------------------
// One block: 32 query rows x full 512 keys for one (b,h).
// 8 warps, each owns a 64-key slice. Whole score row lives in registers.
#define FL_QS_OFF   0
#define FL_KV_OFF   4608
#define FL_MV_OFF   (4608 + 73728)
#define FL_RED_OFF  (4608 + 73728 + 2048)
#define FLASH_SMEM  (4608 + 73728 + 2048 + 1024)

__global__ __launch_bounds__(256) void flash_attn(
    const __nv_bfloat16* __restrict__ qkv,   // [BSc][2304]
    const int* __restrict__ amask,
    __nv_bfloat16* __restrict__ ctx)         // [BSc][768]
{
    extern __shared__ char smx[];
    __nv_bfloat16* Qs  = (__nv_bfloat16*)(smx + FL_QS_OFF);   // [32][72]
    __nv_bfloat16* KVs = (__nv_bfloat16*)(smx + FL_KV_OFF);   // [512][72]
    float* maskv = (float*)(smx + FL_MV_OFF);                 // [512]
    float* red   = (float*)(smx + FL_RED_OFF);                // [8][32]
    float* obuf  = (float*)(smx + FL_KV_OFF);                 // alias: [8][32][64]

    const int tid = threadIdx.x, lane = tid & 31, wid = tid >> 5;
    const int bh = blockIdx.y, b = bh / NHc, h = bh % NHc;
    const int i0 = blockIdx.x * 32;
    const size_t rs = QKVN;
    const __nv_bfloat16* qg = qkv + ((size_t)(b*Sc + i0))*rs + h*DHc;
    const __nv_bfloat16* kg = qkv + ((size_t)b*Sc)*rs + Hc + h*DHc;
    const __nv_bfloat16* vg = qkv + ((size_t)b*Sc)*rs + 2*Hc + h*DHc;

    // load Q (32x64) and K (512x64)
    {
        int r = tid >> 3, c = (tid & 7) * 8;
        cp16(smem_u32(&Qs[r*72 + c]), qg + (size_t)r*rs + c);
        for (int kr = tid >> 3; kr < Sc; kr += 32)
            cp16(smem_u32(&KVs[kr*72 + c]), kg + (size_t)kr*rs + c);
    }
    cp_commit();
    for (int j = tid; j < Sc; j += 256)
        maskv[j] = amask[(size_t)b*Sc + j] ? 0.f : -1e30f;
    cp_wait<0>();
    __syncthreads();

    // ---- scores: acc[mt][nt][e] = Q(32x64) . K_slice(64keys x 64d)^T --------
    float acc[2][8][4];
    #pragma unroll
    for (int i = 0; i < 2; i++)
        #pragma unroll
        for (int j = 0; j < 8; j++)
            #pragma unroll
            for (int e = 0; e < 4; e++) acc[i][j][e] = 0.f;

    const unsigned qsb = smem_u32(Qs), kvb = smem_u32(KVs);
    #pragma unroll
    for (int kk = 0; kk < 4; kk++) {
        unsigned af[2][4];
        #pragma unroll
        for (int mt = 0; mt < 2; mt++) {
            int row = mt*16 + (lane & 15);
            int col = kk*16 + (lane >> 4) * 8;
            ldsm_x4(af[mt], qsb + (row*72 + col)*2);
        }
        unsigned bfr[8][2];
        #pragma unroll
        for (int nt2 = 0; nt2 < 4; nt2++) {
            int row = wid*64 + nt2*16 + (lane & 7) + ((lane >> 4) << 3);
            int col = kk*16 + ((lane >> 3) & 1) * 8;
            unsigned r[4];
            ldsm_x4(r, kvb + (row*72 + col)*2);
            bfr[nt2*2][0] = r[0]; bfr[nt2*2][1] = r[1];
            bfr[nt2*2+1][0] = r[2]; bfr[nt2*2+1][1] = r[3];
        }
        #pragma unroll
        for (int mt = 0; mt < 2; mt++)
            #pragma unroll
            for (int nt = 0; nt < 8; nt++)
                mma16816(acc[mt][nt], af[mt], bfr[nt]);
    }

    __syncthreads();                 // everyone done reading K
    // start V load into the same buffer (overlaps with softmax math)
    {
        int c = (tid & 7) * 8;
        for (int vr = tid >> 3; vr < Sc; vr += 32)
            cp16(smem_u32(&KVs[vr*72 + c]), vg + (size_t)vr*rs + c);
    }
    cp_commit();

    // ---- masked softmax over full row (registers + smem reductions) ---------
    float mcol[8][2];
    #pragma unroll
    for (int nt = 0; nt < 8; nt++) {
        int cbase = wid*64 + nt*8 + (lane & 3)*2;
        mcol[nt][0] = maskv[cbase];
        mcol[nt][1] = maskv[cbase + 1];
    }
    #pragma unroll
    for (int mt = 0; mt < 2; mt++)
        #pragma unroll
        for (int nt = 0; nt < 8; nt++)
            #pragma unroll
            for (int e = 0; e < 4; e++)
                acc[mt][nt][e] = acc[mt][nt][e]*0.125f + mcol[nt][e & 1];

    // 4 row-groups per thread: g = mt*2 + half;  row = mt*16 + (lane>>2) + half*8
    float rmax[4];
    #pragma unroll
    for (int g = 0; g < 4; g++) {
        int mt = g >> 1, half = g & 1;
        float m = -3.4e38f;
        #pragma unroll
        for (int nt = 0; nt < 8; nt++) {
            m = fmaxf(m, acc[mt][nt][half*2]);
            m = fmaxf(m, acc[mt][nt][half*2 + 1]);
        }
        rmax[g] = m;
    }
    #pragma unroll
    for (int g = 0; g < 4; g++) {
        rmax[g] = fmaxf(rmax[g], __shfl_xor_sync(0xffffffffu, rmax[g], 1));
        rmax[g] = fmaxf(rmax[g], __shfl_xor_sync(0xffffffffu, rmax[g], 2));
    }
    if ((lane & 3) == 0) {
        #pragma unroll
        for (int g = 0; g < 4; g++) {
            int row = (g >> 1)*16 + (lane >> 2) + (g & 1)*8;
            red[wid*32 + row] = rmax[g];
        }
    }
    __syncthreads();
    float M[4];
    #pragma unroll
    for (int g = 0; g < 4; g++) {
        int row = (g >> 1)*16 + (lane >> 2) + (g & 1)*8;
        float m = red[row];
        #pragma unroll
        for (int w = 1; w < 8; w++) m = fmaxf(m, red[w*32 + row]);
        M[g] = m;
    }
    __syncthreads();                 // before reusing red for sums

    float rsum[4] = {0.f, 0.f, 0.f, 0.f};
    #pragma unroll
    for (int mt = 0; mt < 2; mt++)
        #pragma unroll
        for (int nt = 0; nt < 8; nt++)
            #pragma unroll
            for (int e = 0; e < 4; e++) {
                int g = mt*2 + (e >> 1);
                float p = exp2f((acc[mt][nt][e] - M[g]) * 1.4426950408889634f);
                acc[mt][nt][e] = p;
                rsum[g] += p;
            }
    #pragma unroll
    for (int g = 0; g < 4; g++) {
        rsum[g] += __shfl_xor_sync(0xffffffffu, rsum[g], 1);
        rsum[g] += __shfl_xor_sync(0xffffffffu, rsum[g], 2);
    }
    if ((lane & 3) == 0) {
        #pragma unroll
        for (int g = 0; g < 4; g++) {
            int row = (g >> 1)*16 + (lane >> 2) + (g & 1)*8;
            red[wid*32 + row] = rsum[g];
        }
    }
    __syncthreads();
    float inv[4];
    #pragma unroll
    for (int g = 0; g < 4; g++) {
        int row = (g >> 1)*16 + (lane >> 2) + (g & 1)*8;
        float s = 0.f;
        #pragma unroll
        for (int w = 0; w < 8; w++) s += red[w*32 + row];
        inv[g] = 1.0f / s;
    }

    // ---- pack P into A fragments (C-frag -> A-frag trick) --------------------
    unsigned aP[2][4][4];
    #pragma unroll
    for (int mt = 0; mt < 2; mt++)
        #pragma unroll
        for (int kb = 0; kb < 4; kb++) {
            float i0v = inv[mt*2], i1v = inv[mt*2 + 1];
            aP[mt][kb][0] = packbf2(acc[mt][2*kb][0]*i0v,   acc[mt][2*kb][1]*i0v);
            aP[mt][kb][1] = packbf2(acc[mt][2*kb][2]*i1v,   acc[mt][2*kb][3]*i1v);
            aP[mt][kb][2] = packbf2(acc[mt][2*kb+1][0]*i0v, acc[mt][2*kb+1][1]*i0v);
            aP[mt][kb][3] = packbf2(acc[mt][2*kb+1][2]*i1v, acc[mt][2*kb+1][3]*i1v);
        }

    // ---- PV: each warp, partial O over its 64-key slice ----------------------
    cp_wait<0>();
    __syncthreads();
    float oacc[2][8][4];
    #pragma unroll
    for (int i = 0; i < 2; i++)
        #pragma unroll
        for (int j = 0; j < 8; j++)
            #pragma unroll
            for (int e = 0; e < 4; e++) oacc[i][j][e] = 0.f;

    #pragma unroll
    for (int kb = 0; kb < 4; kb++) {
        unsigned bv[8][2];
        #pragma unroll
        for (int nt2 = 0; nt2 < 4; nt2++) {
            int row = wid*64 + kb*16 + (lane & 15);
            int col = nt2*16 + (lane >> 4) * 8;
            unsigned r[4];
            ldsm_x4_t(r, kvb + (row*72 + col)*2);
            bv[nt2*2][0] = r[0]; bv[nt2*2][1] = r[1];
            bv[nt2*2+1][0] = r[2]; bv[nt2*2+1][1] = r[3];
        }
        #pragma unroll
        for (int mt = 0; mt < 2; mt++)
            #pragma unroll
            for (int nt = 0; nt < 8; nt++)
                mma16816(oacc[mt][nt], aP[mt][kb], bv[nt]);
    }

    __syncthreads();                 // everyone done reading V; reuse as obuf
    #pragma unroll
    for (int mt = 0; mt < 2; mt++) {
        int row0 = mt*16 + (lane >> 2);
        #pragma unroll
        for (int nt = 0; nt < 8; nt++) {
            int col = nt*8 + (lane & 3)*2;
            *(float2*)&obuf[wid*2048 + row0*64 + col]     = make_float2(oacc[mt][nt][0], oacc[mt][nt][1]);
            *(float2*)&obuf[wid*2048 + (row0+8)*64 + col] = make_float2(oacc[mt][nt][2], oacc[mt][nt][3]);
        }
    }
    __syncthreads();

    // ---- cross-warp reduce + write ctx ---------------------------------------
    {
        float s[8];
        #pragma unroll
        for (int i = 0; i < 8; i++) s[i] = 0.f;
        int base = tid * 8;
        #pragma unroll
        for (int w = 0; w < 8; w++) {
            const float4* p = (const float4*)&obuf[w*2048 + base];
            float4 u0 = p[0], u1 = p[1];
            s[0] += u0.x; s[1] += u0.y; s[2] += u0.z; s[3] += u0.w;
            s[4] += u1.x; s[5] += u1.y; s[6] += u1.z; s[7] += u1.w;
        }
        int row = base >> 6, d0 = base & 63;
        __nv_bfloat162* dst = (__nv_bfloat162*)&ctx[((size_t)(b*Sc + i0 + row))*Hc + h*DHc + d0];
        dst[0] = __floats2bfloat162_rn(s[0], s[1]);
        dst[1] = __floats2bfloat162_rn(s[2], s[3]);
        dst[2] = __floats2bfloat162_rn(s[4], s[5]);
        dst[3] = __floats2bfloat162_rn(s[6], s[7]);
    }
}

// ---------------- emissions = x @ cls_w + cls_b (T=7, fp32) -------------------
__global__ void emissions_kernel(const float* __restrict__ x,
                                 const float* __restrict__ cw,
                                 const float* __restrict__ cb,
                                 float* __restrict__ em)
{
    int token = blockIdx.x;
    int w = threadIdx.x >> 5, lane = threadIdx.x & 31;
    const float* xr = x + (size_t)token*Hc;
    float sum = 0.f;
    for (int c = lane; c < Hc; c += 32) sum += xr[c] * cw[(size_t)c*Tc + w];
    #pragma unroll
    for (int o = 16; o > 0; o >>= 1) sum += __shfl_down_sync(0xffffffffu, sum, o);
    if (lane == 0) em[(size_t)token*Tc + w] = sum + cb[w];
}

// ---------------- CRF ----------------------------------------------------------
__global__ void crf_kernel(const float* __restrict__ em,
                           const int*   __restrict__ labels,
                           const float* __restrict__ cstart,
                           const float* __restrict__ cend,
                           const float* __restrict__ ctrans,
                           float* __restrict__ num_out,
                           float* __restrict__ den_out)
{
    __shared__ float tr[Tc*Tc];
    __shared__ float sbuf[32];
    __shared__ int   s_len;
    int b = blockIdx.x, tid = threadIdx.x;
    const int* lab = labels + (size_t)b*Sc;
    const float* e = em + (size_t)b*Sc*Tc;
    if (tid < Tc*Tc) tr[tid] = ctrans[tid];
    __syncthreads();

    float cnt = 0.f, part = 0.f;
    for (int t = tid; t < Sc; t += blockDim.x) {
        bool m = (t == 0) || (lab[t] != -100);
        if (m) cnt += 1.f;
        if (t >= 1 && lab[t] != -100) {
            int cur = lab[t];
            int prv;
            if (t - 1 == 0) { prv = lab[0]; prv = prv < 0 ? 0 : (prv > Tc-1 ? Tc-1 : prv); }
            else            { prv = lab[t-1]; if (prv == -100) prv = 0; }
            part += tr[prv*Tc + cur] + e[(size_t)t*Tc + cur];
        }
    }
    float totc = block_reduce_sum(cnt, sbuf);
    float tot  = block_reduce_sum(part, sbuf);
    if (tid == 0) {
        int len = (int)(totc + 0.5f);
        s_len = len;
        int s0 = lab[0]; s0 = s0 < 0 ? 0 : (s0 > Tc-1 ? Tc-1 : s0);
        float num = cstart[s0] + e[s0] + tot;
        int send = len - 1;
        int sl;
        if (send == 0) sl = s0;
        else { sl = lab[send]; if (sl == -100) sl = 0; }
        num += cend[sl];
        num_out[b] = num;
    }
    __syncthreads();
    int len = s_len;

    if (tid < 32) {
        int j = tid;
        int jj = (j < Tc) ? j : 0;
        float a = cstart[jj] + e[jj];
        for (int t = 1; t < len; t++) {
            float ej = e[(size_t)t*Tc + jj];
            float av[Tc];
            float m = -3.4028235e+38f;
            #pragma unroll
            for (int i = 0; i < Tc; i++) {
                float ai = __shfl_sync(0xffffffffu, a, i);
                float vv = ai + tr[i*Tc + jj];
                av[i] = vv; m = fmaxf(m, vv);
            }
            float ss = 0.f;
            #pragma unroll
            for (int i = 0; i < Tc; i++) ss += expf(av[i] - m);
            float ne = m + logf(ss) + ej;
            a = (j < Tc) ? ne : a;
        }
        float fa = (j < Tc) ? a + cend[jj] : -3.4028235e+38f;
        float mm = fa;
        #pragma unroll
        for (int o = 16; o > 0; o >>= 1) mm = fmaxf(mm, __shfl_xor_sync(0xffffffffu, mm, o));
        float es = (j < Tc) ? expf(fa - mm) : 0.f;
        #pragma unroll
        for (int o = 16; o > 0; o >>= 1) es += __shfl_xor_sync(0xffffffffu, es, o);
        if (tid == 0) den_out[b] = mm + logf(es);
    }
}

// ---------------- final loss ---------------------------------------------------
__global__ void loss_kernel(const float* __restrict__ num,
                            const float* __restrict__ den,
                            float* __restrict__ out)
{
    int tid = threadIdx.x;
    float v = (tid < Bc) ? (num[tid] - den[tid]) : 0.f;
    #pragma unroll
    for (int o = 16; o > 0; o >>= 1) v += __shfl_down_sync(0xffffffffu, v, o);
    if (tid == 0) out[0] = -v / (float)Bc;
}

// ---------------- host launcher ------------------------------------------------
extern "C" void kernel_launch(void* const* d_in, const int* in_sizes, int n_in,
                              void* d_out, int out_size)
{
    const float* word_emb = (const float*)d_in[0];
    const float* pos_emb  = (const float*)d_in[1];
    const float* emb_ln_s = (const float*)d_in[2];
    const float* emb_ln_b = (const float*)d_in[3];
    const float* attn_qw  = (const float*)d_in[4];
    const float* attn_qb  = (const float*)d_in[5];
    const float* attn_kw  = (const float*)d_in[6];
    const float* attn_kb  = (const float*)d_in[7];
    const float* attn_vw  = (const float*)d_in[8];
    const float* attn_vb  = (const float*)d_in[9];
    const float* attn_ow  = (const float*)d_in[10];
    const float* attn_ob  = (const float*)d_in[11];
    const float* ln1_s    = (const float*)d_in[12];
    const float* ln1_b    = (const float*)d_in[13];
    const float* ffn_w1   = (const float*)d_in[14];
    const float* ffn_b1   = (const float*)d_in[15];
    const float* ffn_w2   = (const float*)d_in[16];
    const float* ffn_b2   = (const float*)d_in[17];
    const float* ln2_s    = (const float*)d_in[18];
    const float* ln2_b    = (const float*)d_in[19];
    const float* cls_w    = (const float*)d_in[20];
    const float* cls_b    = (const float*)d_in[21];
    const float* crf_start= (const float*)d_in[22];
    const float* crf_end  = (const float*)d_in[23];
    const float* crf_trans= (const float*)d_in[24];
    const int* input_ids  = (const int*)d_in[25];
    const int* amask      = (const int*)d_in[26];
    const int* labels     = (const int*)d_in[27];

    float *x, *y, *em, *nb, *db, *bqkv;
    __nv_bfloat16 *xb, *qkv, *ctx, *hb, *wb;
    cudaGetSymbolAddress((void**)&x,    g_x);
    cudaGetSymbolAddress((void**)&xb,   g_xb);
    cudaGetSymbolAddress((void**)&y,    g_y);
    cudaGetSymbolAddress((void**)&qkv,  g_qkv);
    cudaGetSymbolAddress((void**)&ctx,  g_ctx);
    cudaGetSymbolAddress((void**)&hb,   g_h);
    cudaGetSymbolAddress((void**)&wb,   g_wb);
    cudaGetSymbolAddress((void**)&bqkv, g_bqkv);
    cudaGetSymbolAddress((void**)&em,   g_em);
    cudaGetSymbolAddress((void**)&nb,   g_num);
    cudaGetSymbolAddress((void**)&db,   g_den);

    cudaFuncSetAttribute(gemm_mma,  cudaFuncAttributeMaxDynamicSharedMemorySize, GEMM_SMEM);
    cudaFuncSetAttribute(flash_attn, cudaFuncAttributeMaxDynamicSharedMemorySize, FLASH_SMEM);

    const size_t HH = (size_t)Lc*Hc*Hc;       // 3538944
    const size_t HF = (size_t)Lc*Hc*FFc;      // 14155776
    __nv_bfloat16* wqkv = wb;                 // 3*HH packed [L][768][2304]
    __nv_bfloat16* wo   = wb + 3*HH;
    __nv_bfloat16* w1   = wb + 4*HH;
    __nv_bfloat16* w2   = wb + 4*HH + HF;

    pack_qkv_w<<<4096, 256>>>(attn_qw, attn_kw, attn_vw, wqkv);
    pack_qkv_b<<<(Lc*QKVN + 255)/256, 256>>>(attn_qb, attn_kb, attn_vb, bqkv);
    f2b_kernel<<<2048, 256>>>(attn_ow, wo, (int)HH);
    f2b_kernel<<<4096, 256>>>(ffn_w1, w1, (int)HF);
    f2b_kernel<<<4096, 256>>>(ffn_w2, w2, (int)HF);

    embed_ln_kernel<<<BSc, 256>>>(word_emb, pos_emb, emb_ln_s, emb_ln_b, input_ids, x, xb);

    dim3 gQKV(QKVN/128, BSc/128);   // 18 x 128
    dim3 gHH(Hc/128, BSc/128);      // 6 x 128
    dim3 gFF(FFc/128, BSc/128);     // 24 x 128
    for (int i = 0; i < Lc; i++) {
        size_t bOff = (size_t)i*Hc;
        gemm_mma<<<gQKV, 256, GEMM_SMEM>>>(xb, Hc, wqkv + (size_t)i*Hc*QKVN, QKVN,
                                           bqkv + (size_t)i*QKVN, nullptr, qkv, QKVN, Hc, 0);

        flash_attn<<<dim3(Sc/32, Bc*NHc), 256, FLASH_SMEM>>>(qkv, amask, ctx);

        gemm_mma<<<gHH, 256, GEMM_SMEM>>>(ctx, Hc, wo + (size_t)i*Hc*Hc, Hc,
                                          attn_ob + bOff, y, nullptr, Hc, Hc, 0);
        add_ln_kernel<<<BSc, 256>>>(x, y, ln1_s + bOff, ln1_b + bOff, xb);

        gemm_mma<<<gFF, 256, GEMM_SMEM>>>(xb, Hc, w1 + (size_t)i*Hc*FFc, FFc,
                                          ffn_b1 + (size_t)i*FFc, nullptr, hb, FFc, Hc, 1);
        gemm_mma<<<gHH, 256, GEMM_SMEM>>>(hb, FFc, w2 + (size_t)i*FFc*Hc, Hc,
                                          ffn_b2 + bOff, y, nullptr, Hc, FFc, 0);
        add_ln_kernel<<<BSc, 256>>>(x, y, ln2_s + bOff, ln2_b + bOff, xb);
    }

    emissions_kernel<<<BSc, 224>>>(x, cls_w, cls_b, em);
    crf_kernel<<<Bc, 256>>>(em, labels, crf_start, crf_end, crf_trans, nb, db);
    loss_kernel<<<1, 32>>>(nb, db, (float*)d_out);
}